// round 3
// baseline (speedup 1.0000x reference)
#include <cuda_runtime.h>
#include <cuda_bf16.h>
#include <stdint.h>

// Problem constants (fixed by the dataset)
#define N_NODES 100000
#define N_EDGES 3200000
#define DIM 128
#define DIM4 32  // DIM/4

// ---------------- scratch (device globals: allocation-free rule) ----------------
__device__ int   g_is64;
__device__ float g_deg[N_NODES];
__device__ float g_dinv[N_NODES];
__device__ int   g_hist[N_NODES];
__device__ int   g_offs[N_NODES];
__device__ int   g_cursor[N_NODES];
__device__ int   g_srow[N_EDGES];
__device__ float g_scoef[N_EDGES];
__device__ float g_h[(size_t)N_NODES * DIM];   // GEMM output (messages source)
__device__ float g_x2[(size_t)N_NODES * DIM];  // layer-1 output (layer-2 input)

// ---------------- edge index readers (dtype-agnostic) ----------------
__device__ __forceinline__ int read_row(const void* ei, int E, int i) {
    if (g_is64) return (int)((const long long*)ei)[i];
    return ((const int*)ei)[i];
}
__device__ __forceinline__ int read_col(const void* ei, int E, int i) {
    if (g_is64) return (int)((const long long*)ei)[(size_t)E + i];
    return ((const int*)ei)[(size_t)E + i];
}

// ---------------- dtype detection: int64 values < 2^32 have zero high words ----------------
__global__ void detect_kernel(const int* ei_words) {
    if (threadIdx.x == 0) {
        int is64 = 1;
        #pragma unroll 1
        for (int k = 0; k < 64; k++) {
            if (ei_words[2 * k + 1] != 0) { is64 = 0; break; }
        }
        g_is64 = is64;
    }
}

// ---------------- init: deg=1 (self loop), hist=0 ----------------
__global__ void init_kernel(int n) {
    int i = blockIdx.x * blockDim.x + threadIdx.x;
    if (i < n) { g_deg[i] = 1.0f; g_hist[i] = 0; }
}

// ---------------- deg accumulation + in-degree histogram ----------------
__global__ void deg_hist_kernel(const void* __restrict__ ei,
                                const float* __restrict__ ew, int E, int n) {
    int i = blockIdx.x * blockDim.x + threadIdx.x;
    if (i < E) {
        int c = read_col(ei, E, i);
        if ((unsigned)c >= (unsigned)n) return;  // safety
        atomicAdd(&g_deg[c], ew[i]);
        atomicAdd(&g_hist[c], 1);
    }
}

// ---------------- dinv = rsqrt(deg) ----------------
__global__ void dinv_kernel(int n) {
    int i = blockIdx.x * blockDim.x + threadIdx.x;
    if (i < n) {
        float d = g_deg[i];
        g_dinv[i] = (d > 0.0f) ? rsqrtf(d) : 0.0f;
    }
}

// ---------------- single-block exclusive scan of hist -> offs, cursor ----------------
__global__ void scan_kernel(int n) {
    __shared__ int warp_off[32];
    __shared__ int s_total;
    int tid = threadIdx.x, lane = tid & 31, wid = tid >> 5;
    int run = 0;
    for (int base = 0; base < n; base += 1024) {
        int i = base + tid;
        int v = (i < n) ? g_hist[i] : 0;
        int incl = v;
        #pragma unroll
        for (int s = 1; s < 32; s <<= 1) {
            int t = __shfl_up_sync(0xffffffffu, incl, s);
            if (lane >= s) incl += t;
        }
        if (lane == 31) warp_off[wid] = incl;
        __syncthreads();
        if (wid == 0) {
            int ws = warp_off[lane];
            int wincl = ws;
            #pragma unroll
            for (int s = 1; s < 32; s <<= 1) {
                int t = __shfl_up_sync(0xffffffffu, wincl, s);
                if (lane >= s) wincl += t;
            }
            warp_off[lane] = wincl - ws;  // exclusive warp offset
            if (lane == 31) s_total = wincl;
        }
        __syncthreads();
        int excl = run + warp_off[wid] + incl - v;
        if (i < n) { g_offs[i] = excl; g_cursor[i] = excl; }
        run += s_total;
        __syncthreads();
    }
}

// ---------------- scatter edges into CSR bins (coef = ew * dinv[row]) ----------------
__global__ void scatter_kernel(const void* __restrict__ ei,
                               const float* __restrict__ ew, int E, int n) {
    int i = blockIdx.x * blockDim.x + threadIdx.x;
    if (i < E) {
        int r = read_row(ei, E, i);
        int c = read_col(ei, E, i);
        if ((unsigned)r >= (unsigned)n || (unsigned)c >= (unsigned)n) return;  // safety
        int pos = atomicAdd(&g_cursor[c], 1);
        if ((unsigned)pos < (unsigned)E) {
            g_srow[pos] = r;
            g_scoef[pos] = ew[i] * g_dinv[r];
        }
    }
}

// ---------------- GEMM: g_h = x @ W  (N x 128 @ 128 x 128) ----------------
// K-tiled: W loaded in two 64-row halves into 32KB static smem.
// block: 256 threads = 8 warps; each warp computes 4 rows; lane covers cols [4l,4l+3]
__global__ void gemm_kernel(const float* __restrict__ x_ext,
                            const float* __restrict__ W,
                            int use_x2, int n) {
    __shared__ float4 Ws4[64 * DIM4];  // 64 k-rows x 128 cols = 32KB

    const float* x = use_x2 ? (const float*)g_x2 : x_ext;
    const float4* X4 = (const float4*)x;
    const float4* W4 = (const float4*)W;
    float4* H4 = (float4*)g_h;

    int lane = threadIdx.x & 31, wid = threadIdx.x >> 5;
    int r0 = blockIdx.x * 32 + wid * 4;

    float4 acc[4];
    #pragma unroll
    for (int ri = 0; ri < 4; ri++) acc[ri] = make_float4(0.f, 0.f, 0.f, 0.f);

    #pragma unroll
    for (int half = 0; half < 2; half++) {
        const float4* Wh = W4 + (size_t)half * 64 * DIM4;
        for (int idx = threadIdx.x; idx < 64 * DIM4; idx += 256)
            Ws4[idx] = Wh[idx];
        __syncthreads();

        if (r0 < n) {
            #pragma unroll 4
            for (int kk = 0; kk < 16; kk++) {
                float4 w0 = Ws4[(4 * kk + 0) * DIM4 + lane];
                float4 w1 = Ws4[(4 * kk + 1) * DIM4 + lane];
                float4 w2 = Ws4[(4 * kk + 2) * DIM4 + lane];
                float4 w3 = Ws4[(4 * kk + 3) * DIM4 + lane];
                #pragma unroll
                for (int ri = 0; ri < 4; ri++) {
                    int r = r0 + ri;
                    if (r < n) {
                        float4 xv = X4[(size_t)r * DIM4 + half * 16 + kk];
                        acc[ri].x += xv.x * w0.x + xv.y * w1.x + xv.z * w2.x + xv.w * w3.x;
                        acc[ri].y += xv.x * w0.y + xv.y * w1.y + xv.z * w2.y + xv.w * w3.y;
                        acc[ri].z += xv.x * w0.z + xv.y * w1.z + xv.z * w2.z + xv.w * w3.z;
                        acc[ri].w += xv.x * w0.w + xv.y * w1.w + xv.z * w2.w + xv.w * w3.w;
                    }
                }
            }
        }
        __syncthreads();
    }

    #pragma unroll
    for (int ri = 0; ri < 4; ri++) {
        int r = r0 + ri;
        if (r < n) H4[(size_t)r * DIM4 + lane] = acc[ri];
    }
}

// ---------------- pull aggregation: one warp per node, no atomics ----------------
// dst[i] = dinv[i] * sum_e coef_e * g_h[row_e]  +  dinv[i]^2 * g_h[i]  +  b ; optional relu
__global__ void agg_kernel(const float* __restrict__ bias,
                           float* __restrict__ out_ext,
                           int n, int do_relu, int dst_is_x2) {
    int gw = (blockIdx.x * blockDim.x + threadIdx.x) >> 5;
    int lane = threadIdx.x & 31;
    if (gw >= n) return;
    int i = gw;
    int off = g_offs[i];
    int cnt = g_hist[i];
    int end = off + cnt;

    const float4* H = (const float4*)g_h;
    float4 a0 = make_float4(0.f, 0.f, 0.f, 0.f);
    float4 a1 = make_float4(0.f, 0.f, 0.f, 0.f);

    int e = off;
    for (; e + 1 < end; e += 2) {
        int   r0 = g_srow[e];     float c0 = g_scoef[e];
        int   r1 = g_srow[e + 1]; float c1 = g_scoef[e + 1];
        float4 h0 = H[(size_t)r0 * DIM4 + lane];
        float4 h1 = H[(size_t)r1 * DIM4 + lane];
        a0.x += c0 * h0.x; a0.y += c0 * h0.y; a0.z += c0 * h0.z; a0.w += c0 * h0.w;
        a1.x += c1 * h1.x; a1.y += c1 * h1.y; a1.z += c1 * h1.z; a1.w += c1 * h1.w;
    }
    if (e < end) {
        int r0 = g_srow[e]; float c0 = g_scoef[e];
        float4 h0 = H[(size_t)r0 * DIM4 + lane];
        a0.x += c0 * h0.x; a0.y += c0 * h0.y; a0.z += c0 * h0.z; a0.w += c0 * h0.w;
    }

    float di = g_dinv[i];
    float d2 = di * di;
    float4 self = H[(size_t)i * DIM4 + lane];
    float4 b4 = ((const float4*)bias)[lane];

    float4 r;
    r.x = di * (a0.x + a1.x) + d2 * self.x + b4.x;
    r.y = di * (a0.y + a1.y) + d2 * self.y + b4.y;
    r.z = di * (a0.z + a1.z) + d2 * self.z + b4.z;
    r.w = di * (a0.w + a1.w) + d2 * self.w + b4.w;
    if (do_relu) {
        r.x = fmaxf(r.x, 0.f); r.y = fmaxf(r.y, 0.f);
        r.z = fmaxf(r.z, 0.f); r.w = fmaxf(r.w, 0.f);
    }
    float4* dst = dst_is_x2 ? (float4*)g_x2 : (float4*)out_ext;
    dst[(size_t)i * DIM4 + lane] = r;
}

// ---------------- launch (kernel launches ONLY — graph-capturable) ----------------
extern "C" void kernel_launch(void* const* d_in, const int* in_sizes, int n_in,
                              void* d_out, int out_size) {
    const float* x  = (const float*)d_in[0];
    const void*  ei = d_in[1];                 // [2, E], int32 OR int64
    const float* ew = (const float*)d_in[2];
    const float* W1 = (const float*)d_in[3];
    const float* b1 = (const float*)d_in[4];
    const float* W2 = (const float*)d_in[5];
    const float* b2 = (const float*)d_in[6];
    float* out = (float*)d_out;

    int n = in_sizes[0] / DIM;   // 100000
    int E = in_sizes[2];         // 3200000

    int nb_n  = (n + 255) / 256;
    int nb_e  = (E + 255) / 256;
    int nb_wn = (n * 32 + 255) / 256;  // one warp per node
    int nb_g  = (n + 31) / 32;

    // preprocessing (CSR-ize by destination)
    detect_kernel<<<1, 32>>>((const int*)ei);
    init_kernel<<<nb_n, 256>>>(n);
    deg_hist_kernel<<<nb_e, 256>>>(ei, ew, E, n);
    dinv_kernel<<<nb_n, 256>>>(n);
    scan_kernel<<<1, 1024>>>(n);
    scatter_kernel<<<nb_e, 256>>>(ei, ew, E, n);

    // layer 1: g_h = x @ W1 ; g_x2 = agg(g_h) + b1, relu
    gemm_kernel<<<nb_g, 256>>>(x, W1, /*use_x2=*/0, n);
    agg_kernel<<<nb_wn, 256>>>(b1, out, n, /*relu=*/1, /*dst_is_x2=*/1);

    // layer 2: g_h = g_x2 @ W2 ; out = agg(g_h) + b2
    gemm_kernel<<<nb_g, 256>>>(x, W2, /*use_x2=*/1, n);
    agg_kernel<<<nb_wn, 256>>>(b2, out, n, /*relu=*/0, /*dst_is_x2=*/0);
}

// round 5
// speedup vs baseline: 1.3600x; 1.3600x over previous
#include <cuda_runtime.h>
#include <cuda_fp16.h>
#include <cuda_bf16.h>
#include <stdint.h>

#define N_NODES 100000
#define N_EDGES 3200000
#define DIM 128
#define DIM4 32
#define SCAN_NB 98   // ceil(100000/1024)

// ---------------- scratch (device globals) ----------------
__device__ int   g_is64;
__device__ float g_deg[N_NODES];
__device__ float g_dinv[N_NODES];
__device__ int   g_hist[N_NODES];
__device__ int   g_offs[N_NODES];
__device__ int   g_cursor[N_NODES];
__device__ int2  g_edge[N_EDGES];                 // (src row, coef bits)
__device__ int   g_psum[256];
__device__ int   g_poff[256];
__device__ uint4 g_h16[(size_t)N_NODES * 16];     // fp16 messages: 128 halfs/row
__device__ float g_x2[(size_t)N_NODES * DIM];     // layer-1 output (fp32)

// ---------------- edge index readers (dtype-agnostic) ----------------
__device__ __forceinline__ int read_row(const void* ei, int E, int i) {
    if (g_is64) return (int)((const long long*)ei)[i];
    return ((const int*)ei)[i];
}
__device__ __forceinline__ int read_col(const void* ei, int E, int i) {
    if (g_is64) return (int)((const long long*)ei)[(size_t)E + i];
    return ((const int*)ei)[(size_t)E + i];
}

// ---------------- init: deg=1, hist=0; block 0 also detects dtype ----------------
__global__ void init_kernel(const int* ei_words, int n) {
    int i = blockIdx.x * blockDim.x + threadIdx.x;
    if (i < n) { g_deg[i] = 1.0f; g_hist[i] = 0; }
    if (blockIdx.x == 0 && threadIdx.x == 0) {
        int is64 = 1;
        #pragma unroll 1
        for (int k = 0; k < 64; k++)
            if (ei_words[2 * k + 1] != 0) { is64 = 0; break; }
        g_is64 = is64;
    }
}

// ---------------- deg accumulation + in-degree histogram ----------------
__global__ void deg_hist_kernel(const void* __restrict__ ei,
                                const float* __restrict__ ew, int E, int n) {
    int i = blockIdx.x * blockDim.x + threadIdx.x;
    if (i < E) {
        int c = read_col(ei, E, i);
        if ((unsigned)c >= (unsigned)n) return;
        atomicAdd(&g_deg[c], ew[i]);
        atomicAdd(&g_hist[c], 1);
    }
}

// ---------------- scan phase 1: per-block partial sums of hist; fused dinv ----------------
__global__ __launch_bounds__(256) void scan_phase1(int n) {
    __shared__ int ws[8];
    int b = blockIdx.x, tid = threadIdx.x;
    int base = b * 1024;
    int s = 0;
    #pragma unroll
    for (int j = 0; j < 4; j++) {
        int i = base + j * 256 + tid;
        if (i < n) {
            s += g_hist[i];
            float d = g_deg[i];
            g_dinv[i] = (d > 0.0f) ? rsqrtf(d) : 0.0f;
        }
    }
    #pragma unroll
    for (int o = 16; o; o >>= 1) s += __shfl_xor_sync(0xffffffffu, s, o);
    if ((tid & 31) == 0) ws[tid >> 5] = s;
    __syncthreads();
    if (tid == 0) {
        int t = 0;
        #pragma unroll
        for (int j = 0; j < 8; j++) t += ws[j];
        g_psum[b] = t;
    }
}

// ---------------- scan phase 2: single warp scans the 98 partials ----------------
__global__ void scan_phase2() {
    int lane = threadIdx.x;
    int carry = 0;
    #pragma unroll
    for (int base = 0; base < SCAN_NB; base += 32) {
        int i = base + lane;
        int v = (i < SCAN_NB) ? g_psum[i] : 0;
        int incl = v;
        #pragma unroll
        for (int s = 1; s < 32; s <<= 1) {
            int t = __shfl_up_sync(0xffffffffu, incl, s);
            if (lane >= s) incl += t;
        }
        if (i < SCAN_NB) g_poff[i] = carry + incl - v;
        carry += __shfl_sync(0xffffffffu, incl, 31);
    }
}

// ---------------- scan phase 3: local exclusive scan + block offset ----------------
__global__ __launch_bounds__(256) void scan_phase3(int n) {
    __shared__ int wsum[8];
    int b = blockIdx.x, tid = threadIdx.x, lane = tid & 31, wid = tid >> 5;
    int base = b * 1024 + tid * 4;
    int v0 = 0, v1 = 0, v2 = 0, v3 = 0;
    if (base + 3 < n) {
        int4 v = *(const int4*)&g_hist[base];
        v0 = v.x; v1 = v.y; v2 = v.z; v3 = v.w;
    } else {
        if (base + 0 < n) v0 = g_hist[base + 0];
        if (base + 1 < n) v1 = g_hist[base + 1];
        if (base + 2 < n) v2 = g_hist[base + 2];
        if (base + 3 < n) v3 = g_hist[base + 3];
    }
    int t = v0 + v1 + v2 + v3;
    int incl = t;
    #pragma unroll
    for (int s = 1; s < 32; s <<= 1) {
        int u = __shfl_up_sync(0xffffffffu, incl, s);
        if (lane >= s) incl += u;
    }
    if (lane == 31) wsum[wid] = incl;
    __syncthreads();
    if (tid == 0) {
        int run = 0;
        #pragma unroll
        for (int j = 0; j < 8; j++) { int u = wsum[j]; wsum[j] = run; run += u; }
    }
    __syncthreads();
    int excl = g_poff[b] + wsum[wid] + incl - t;
    if (base + 0 < n) { g_offs[base + 0] = excl; g_cursor[base + 0] = excl; } excl += v0;
    if (base + 1 < n) { g_offs[base + 1] = excl; g_cursor[base + 1] = excl; } excl += v1;
    if (base + 2 < n) { g_offs[base + 2] = excl; g_cursor[base + 2] = excl; } excl += v2;
    if (base + 3 < n) { g_offs[base + 3] = excl; g_cursor[base + 3] = excl; }
}

// ---------------- scatter edges into CSR bins; single int2 store per edge ----------------
__global__ void scatter_kernel(const void* __restrict__ ei,
                               const float* __restrict__ ew, int E, int n) {
    int i = blockIdx.x * blockDim.x + threadIdx.x;
    if (i < E) {
        int r = read_row(ei, E, i);
        int c = read_col(ei, E, i);
        if ((unsigned)r >= (unsigned)n || (unsigned)c >= (unsigned)n) return;
        int pos = atomicAdd(&g_cursor[c], 1);
        if ((unsigned)pos < (unsigned)E)
            g_edge[pos] = make_int2(r, __float_as_int(ew[i] * g_dinv[r]));
    }
}

// ---------------- f32x2 helpers ----------------
__device__ __forceinline__ unsigned long long dup2(float v) {
    unsigned long long d;
    asm("mov.b64 %0, {%1, %1};" : "=l"(d) : "f"(v));
    return d;
}
__device__ __forceinline__ unsigned long long fma2(unsigned long long a,
                                                   unsigned long long b,
                                                   unsigned long long c) {
    unsigned long long d;
    asm("fma.rn.f32x2 %0, %1, %2, %3;" : "=l"(d) : "l"(a), "l"(b), "l"(c));
    return d;
}
__device__ __forceinline__ float2 unpack2(unsigned long long v) {
    float2 f;
    f.x = __uint_as_float((unsigned)(v & 0xffffffffull));
    f.y = __uint_as_float((unsigned)(v >> 32));
    return f;
}

// ---------------- GEMM: g_h16 = (x @ W) as fp16  (N x 128 @ 128 x 128) ----------------
// packed-pair FFMA2 math; W K-halves staged in 32KB static smem.
__global__ __launch_bounds__(256) void gemm_kernel(const float* __restrict__ x_ext,
                                                   const float* __restrict__ W,
                                                   int use_x2, int n) {
    __shared__ ulonglong2 Ws[64 * DIM4];  // 64 k-rows x 128 cols (as 2x f32x2) = 32KB

    const float* x = use_x2 ? (const float*)g_x2 : x_ext;
    const float4* X4 = (const float4*)x;

    int lane = threadIdx.x & 31, wid = threadIdx.x >> 5;
    int r0 = blockIdx.x * 32 + wid * 4;

    unsigned long long a01[4], a23[4];
    #pragma unroll
    for (int ri = 0; ri < 4; ri++) { a01[ri] = 0ull; a23[ri] = 0ull; }

    #pragma unroll
    for (int half = 0; half < 2; half++) {
        const ulonglong2* Wh = (const ulonglong2*)(W + (size_t)half * 64 * DIM);
        for (int idx = threadIdx.x; idx < 64 * DIM4; idx += 256)
            Ws[idx] = Wh[idx];
        __syncthreads();

        if (r0 < n) {
            #pragma unroll 4
            for (int kk = 0; kk < 16; kk++) {
                ulonglong2 w0 = Ws[(4 * kk + 0) * DIM4 + lane];
                ulonglong2 w1 = Ws[(4 * kk + 1) * DIM4 + lane];
                ulonglong2 w2 = Ws[(4 * kk + 2) * DIM4 + lane];
                ulonglong2 w3 = Ws[(4 * kk + 3) * DIM4 + lane];
                #pragma unroll
                for (int ri = 0; ri < 4; ri++) {
                    int r = r0 + ri;
                    if (r < n) {
                        float4 xv = X4[(size_t)r * DIM4 + half * 16 + kk];
                        unsigned long long x0 = dup2(xv.x), x1 = dup2(xv.y);
                        unsigned long long x2 = dup2(xv.z), x3 = dup2(xv.w);
                        a01[ri] = fma2(x0, w0.x, a01[ri]); a23[ri] = fma2(x0, w0.y, a23[ri]);
                        a01[ri] = fma2(x1, w1.x, a01[ri]); a23[ri] = fma2(x1, w1.y, a23[ri]);
                        a01[ri] = fma2(x2, w2.x, a01[ri]); a23[ri] = fma2(x2, w2.y, a23[ri]);
                        a01[ri] = fma2(x3, w3.x, a01[ri]); a23[ri] = fma2(x3, w3.y, a23[ri]);
                    }
                }
            }
        }
        __syncthreads();
    }

    uint2* H2 = (uint2*)g_h16;  // row = 32 x uint2 (256B of fp16)
    #pragma unroll
    for (int ri = 0; ri < 4; ri++) {
        int r = r0 + ri;
        if (r < n) {
            float2 c01 = unpack2(a01[ri]);
            float2 c23 = unpack2(a23[ri]);
            __half2 p0 = __floats2half2_rn(c01.x, c01.y);
            __half2 p1 = __floats2half2_rn(c23.x, c23.y);
            uint2 o;
            o.x = *(unsigned*)&p0;
            o.y = *(unsigned*)&p1;
            H2[(size_t)r * 32 + lane] = o;
        }
    }
}

// ---------------- pull aggregation (fp16 gather): one warp per node, 2 edges/iter ----------------
// dst[i] = dinv[i]*sum_e coef_e*h16[src_e] + dinv[i]^2*h16[i] + b ; optional relu
__global__ __launch_bounds__(256) void agg_kernel(const float* __restrict__ bias,
                                                  float* __restrict__ out_ext,
                                                  int n, int do_relu, int dst_is_x2) {
    int gw = (blockIdx.x * blockDim.x + threadIdx.x) >> 5;
    int lane = threadIdx.x & 31;
    if (gw >= n) return;
    int i = gw;
    int half = lane >> 4;    // which of 2 concurrent edges
    int li = lane & 15;      // 16B chunk within the 256B fp16 row

    int off = g_offs[i];
    int end = off + g_hist[i];

    float acc[8];
    #pragma unroll
    for (int j = 0; j < 8; j++) acc[j] = 0.0f;

    #pragma unroll 2
    for (int e0 = off; e0 < end; e0 += 2) {
        int e = e0 + half;
        if (e < end) {
            int2 ed = g_edge[e];
            float c = __int_as_float(ed.y);
            uint4 v = g_h16[(size_t)ed.x * 16 + li];
            __half2* hp = (__half2*)&v;
            float2 f0 = __half22float2(hp[0]);
            float2 f1 = __half22float2(hp[1]);
            float2 f2 = __half22float2(hp[2]);
            float2 f3 = __half22float2(hp[3]);
            acc[0] += c * f0.x; acc[1] += c * f0.y;
            acc[2] += c * f1.x; acc[3] += c * f1.y;
            acc[4] += c * f2.x; acc[5] += c * f2.y;
            acc[6] += c * f3.x; acc[7] += c * f3.y;
        }
    }
    // combine the two edge-halves: every lane ends with the full 8-col sum
    #pragma unroll
    for (int j = 0; j < 8; j++)
        acc[j] += __shfl_xor_sync(0xffffffffu, acc[j], 16);

    float di = g_dinv[i];
    float d2 = di * di;
    uint4 sv = g_h16[(size_t)i * 16 + li];
    __half2* sh = (__half2*)&sv;
    float2 s0 = __half22float2(sh[2 * half + 0]);
    float2 s1 = __half22float2(sh[2 * half + 1]);
    float4 b4 = ((const float4*)bias)[li * 2 + half];

    float4 r;
    r.x = di * acc[4 * half + 0] + d2 * s0.x + b4.x;
    r.y = di * acc[4 * half + 1] + d2 * s0.y + b4.y;
    r.z = di * acc[4 * half + 2] + d2 * s1.x + b4.z;
    r.w = di * acc[4 * half + 3] + d2 * s1.y + b4.w;
    if (do_relu) {
        r.x = fmaxf(r.x, 0.f); r.y = fmaxf(r.y, 0.f);
        r.z = fmaxf(r.z, 0.f); r.w = fmaxf(r.w, 0.f);
    }
    float4* dst = dst_is_x2 ? (float4*)g_x2 : (float4*)out_ext;
    dst[(size_t)i * 32 + li * 2 + half] = r;
}

// ---------------- launch (kernel launches ONLY — graph-capturable) ----------------
extern "C" void kernel_launch(void* const* d_in, const int* in_sizes, int n_in,
                              void* d_out, int out_size) {
    const float* x  = (const float*)d_in[0];
    const void*  ei = d_in[1];                 // [2, E], int32 OR int64
    const float* ew = (const float*)d_in[2];
    const float* W1 = (const float*)d_in[3];
    const float* b1 = (const float*)d_in[4];
    const float* W2 = (const float*)d_in[5];
    const float* b2 = (const float*)d_in[6];
    float* out = (float*)d_out;

    int n = in_sizes[0] / DIM;   // 100000
    int E = in_sizes[2];         // 3200000

    int nb_n  = (n + 255) / 256;
    int nb_e  = (E + 511) / 512;
    int nb_wn = (n * 32 + 255) / 256;  // one warp per node
    int nb_g  = (n + 31) / 32;
    int nb_s  = (n + 1023) / 1024;

    // preprocessing: CSR-ize edges by destination
    init_kernel<<<nb_n, 256>>>((const int*)ei, n);
    deg_hist_kernel<<<nb_e, 512>>>(ei, ew, E, n);
    scan_phase1<<<nb_s, 256>>>(n);
    scan_phase2<<<1, 32>>>();
    scan_phase3<<<nb_s, 256>>>(n);
    scatter_kernel<<<nb_e, 512>>>(ei, ew, E, n);

    // layer 1: g_h16 = fp16(x @ W1) ; g_x2 = agg + b1, relu
    gemm_kernel<<<nb_g, 256>>>(x, W1, /*use_x2=*/0, n);
    agg_kernel<<<nb_wn, 256>>>(b1, out, n, /*relu=*/1, /*dst_is_x2=*/1);

    // layer 2: g_h16 = fp16(g_x2 @ W2) ; out = agg + b2
    gemm_kernel<<<nb_g, 256>>>(x, W2, /*use_x2=*/1, n);
    agg_kernel<<<nb_wn, 256>>>(b2, out, n, /*relu=*/0, /*dst_is_x2=*/0);
}